// round 5
// baseline (speedup 1.0000x reference)
#include <cuda_runtime.h>
#include <math.h>

#define B_ 8
#define T_ 1024
#define C_ 32
#define F_ 256
#define D_ 128
#define K_ 512
#define Q_ (B_*T_)      // 8192
#define KC 64
#define NKC (K_/KC)     // 8
#define QT 32
#define NQT (Q_/QT)     // 256
#define NREP 4          // G atomic replicas

// ---------------- scratch (no allocations allowed) ----------------
__device__ float g_bd[NKC*Q_];
__device__ int   g_bi[NKC*Q_];
__device__ float g_Gr[NREP*C_*F_];
__device__ float g_S[F_];
__device__ float g_acc[2];   // [0] = sum E^2, [1] = sum (h-z)^2

#define ABSMASK 0x7fffffff7fffffffULL

__device__ __forceinline__ unsigned long long fadd2u(unsigned long long a,
                                                     unsigned long long b) {
    unsigned long long r;
    asm("add.rn.f32x2 %0, %1, %2;" : "=l"(r) : "l"(a), "l"(b));
    return r;
}

// ---------------- zero accumulators ----------------
__global__ void zero_kernel() {
    int g = blockIdx.x * 256 + threadIdx.x;
    if (g < NREP*C_*F_) g_Gr[g] = 0.f;
    if (g < F_)         g_S[g] = 0.f;
    if (g < 2)          g_acc[g] = 0.f;
}

// ---------------- L1 NN search: packed diff + packed abs + packed acc ------
// 2048 CTAs (256 q-tiles x 8 k-chunks), 256 threads. CTA = 32 q x 64 k.
// Thread tile 2q x 4k as 4 u64 accumulators. Per d: 4 fadd2 (diff, fma pipe),
// 4 u64 AND (8 LOP3, alu pipe), 4 fadd2 (acc, fma pipe) -> 1.0 fma instr/elem.
__global__ void nn4_kernel(const float* __restrict__ H, const float* __restrict__ M) {
    extern __shared__ char smem[];
    float2* h2_s = (float2*)smem;              // [128][32] (h,h) duplicated, 32KB
    float*  m_s  = (float*)(smem + 32*1024);   // [128][64] negated, 32KB

    int tid = threadIdx.x;
    int qt = blockIdx.x & (NQT - 1);
    int kc = blockIdx.x >> 8;
    int q0 = qt * QT;
    int b  = q0 >> 10;
    int t0 = q0 & (T_ - 1);
    int k0 = kc * KC;

    for (int e = tid; e < D_*QT; e += 256) {
        int d = e >> 5, q = e & 31;
        float v = H[b*(D_*T_) + d*T_ + t0 + q];
        h2_s[e] = make_float2(v, v);
    }
    for (int e = tid; e < (D_*KC)/4; e += 256) {
        int d = e >> 4, c4 = e & 15;
        float4 mv = *(const float4*)&M[d*K_ + k0 + c4*4];
        *(float4*)&m_s[d*KC + c4*4] = make_float4(-mv.x, -mv.y, -mv.z, -mv.w);
    }
    __syncthreads();

    int tk = tid & 15, tq = tid >> 4;   // 16 k-groups x 16 q-groups
    int qq = tq * 2, kk = tk * 4;       // 16B-consecutive m loads: conflict-free

    unsigned long long a0=0ULL, a1=0ULL, a2=0ULL, a3=0ULL;
    #pragma unroll 4
    for (int d = 0; d < D_; d++) {
        ulonglong2 hh = *(const ulonglong2*)&h2_s[d*QT + qq];   // (h0,h0),(h1,h1)
        ulonglong2 mm = *(const ulonglong2*)&m_s[d*KC + kk];    // (-k0,-k1),(-k2,-k3)
        a0 = fadd2u(a0, fadd2u(hh.x, mm.x) & ABSMASK);
        a1 = fadd2u(a1, fadd2u(hh.x, mm.y) & ABSMASK);
        a2 = fadd2u(a2, fadd2u(hh.y, mm.x) & ABSMASK);
        a3 = fadd2u(a3, fadd2u(hh.y, mm.y) & ABSMASK);
    }

    // unpack: a0 = q0:(k0,k1)  a1 = q0:(k2,k3)  a2 = q1:(k0,k1)  a3 = q1:(k2,k3)
    float c0 = __uint_as_float((unsigned)(a0 & 0xffffffffu));
    float c1 = __uint_as_float((unsigned)(a0 >> 32));
    float c2 = __uint_as_float((unsigned)(a1 & 0xffffffffu));
    float c3 = __uint_as_float((unsigned)(a1 >> 32));
    float bd0 = c0; int bi0 = k0 + kk;
    if (c1 < bd0) { bd0 = c1; bi0 = k0 + kk + 1; }
    if (c2 < bd0) { bd0 = c2; bi0 = k0 + kk + 2; }
    if (c3 < bd0) { bd0 = c3; bi0 = k0 + kk + 3; }
    c0 = __uint_as_float((unsigned)(a2 & 0xffffffffu));
    c1 = __uint_as_float((unsigned)(a2 >> 32));
    c2 = __uint_as_float((unsigned)(a3 & 0xffffffffu));
    c3 = __uint_as_float((unsigned)(a3 >> 32));
    float bd1 = c0; int bi1 = k0 + kk;
    if (c1 < bd1) { bd1 = c1; bi1 = k0 + kk + 1; }
    if (c2 < bd1) { bd1 = c2; bi1 = k0 + kk + 2; }
    if (c3 < bd1) { bd1 = c3; bi1 = k0 + kk + 3; }

    // lexicographic min across the 16 tk lanes (first-argmin semantics)
    #pragma unroll
    for (int off = 1; off < 16; off <<= 1) {
        float od = __shfl_xor_sync(0xffffffffu, bd0, off);
        int   oi = __shfl_xor_sync(0xffffffffu, bi0, off);
        if (od < bd0 || (od == bd0 && oi < bi0)) { bd0 = od; bi0 = oi; }
        od = __shfl_xor_sync(0xffffffffu, bd1, off);
        oi = __shfl_xor_sync(0xffffffffu, bi1, off);
        if (od < bd1 || (od == bd1 && oi < bi1)) { bd1 = od; bi1 = oi; }
    }
    if (tk == 0) {
        g_bd[kc*Q_ + q0 + qq    ] = bd0;  g_bi[kc*Q_ + q0 + qq    ] = bi0;
        g_bd[kc*Q_ + q0 + qq + 1] = bd1;  g_bi[kc*Q_ + q0 + qq + 1] = bi1;
    }
}

// ---------------- combine K-chunks, compute sum (h - z)^2 ----------------
__global__ void nnred_kernel(const float* __restrict__ H, const float* __restrict__ M) {
    int tid = threadIdx.x;
    int q = blockIdx.x * 256 + tid;
    float bd = g_bd[q]; int bi = g_bi[q];
    #pragma unroll
    for (int c = 1; c < NKC; c++) {
        float dd = g_bd[c*Q_ + q]; int ii = g_bi[c*Q_ + q];
        if (dd < bd) { bd = dd; bi = ii; }   // chunks ascend in k
    }
    int b = q >> 10, t = q & (T_ - 1);
    const float* h = H + b*(D_*T_) + t;
    float s = 0.f;
    #pragma unroll 8
    for (int d = 0; d < D_; d++) {
        float diff = h[d*T_] - M[d*K_ + bi];
        s += diff * diff;
    }
    #pragma unroll
    for (int off = 16; off > 0; off >>= 1) s += __shfl_down_sync(0xffffffffu, s, off);
    __shared__ float red[8];
    int warp = tid >> 5, lane = tid & 31;
    if (lane == 0) red[warp] = s;
    __syncthreads();
    if (tid == 0) {
        float tot = 0.f;
        #pragma unroll
        for (int i = 0; i < 8; i++) tot += red[i];
        atomicAdd(&g_acc[1], tot);
    }
}

// ---------------- fused decoder: E tile, sumE^2, S partial, G partial ----
// 512 CTAs x 256 threads, 16 rows each -> ~3.5 CTA/SM resident.
__global__ void dec_kernel(const float* __restrict__ Hdec, const float* __restrict__ W,
                           const float* __restrict__ X) {
    extern __shared__ char smem[];
    float* hd_s = (float*)smem;                    // [16][256]  16KB
    float* e_s  = (float*)(smem + 16384);          // [16][32]    2KB
    float* w_s  = (float*)(smem + 16384 + 2048);   // [256][33]  33KB padded
    __shared__ float red[8];

    int tid = threadIdx.x;
    int r0 = blockIdx.x * 16;
    int warp = tid >> 5, lane = tid & 31;

    for (int e = tid; e < C_*F_; e += 256) {
        int c = e >> 8, f = e & 255;
        w_s[f*33 + c] = W[e];            // coalesced read, conflict-free STS
    }
    {
        const float4* src = (const float4*)(Hdec + (size_t)r0 * F_);
        float4* dst = (float4*)hd_s;
        #pragma unroll
        for (int i = 0; i < 4; i++) dst[tid + i*256] = src[tid + i*256];
    }
    __syncthreads();

    // phase 2: E = Hdec W^T - X. warp = 2-row group, lane = channel c
    float acc0 = 0.f, acc1 = 0.f;
    for (int f = 0; f < F_; f += 4) {
        float w0 = w_s[(f+0)*33 + lane];
        float w1 = w_s[(f+1)*33 + lane];
        float w2 = w_s[(f+2)*33 + lane];
        float w3 = w_s[(f+3)*33 + lane];
        float4 a4 = *(const float4*)&hd_s[(warp*2    )*F_ + f];   // broadcast
        float4 b4 = *(const float4*)&hd_s[(warp*2 + 1)*F_ + f];
        acc0 = fmaf(a4.x, w0, fmaf(a4.y, w1, fmaf(a4.z, w2, fmaf(a4.w, w3, acc0))));
        acc1 = fmaf(b4.x, w0, fmaf(b4.y, w1, fmaf(b4.z, w2, fmaf(b4.w, w3, acc1))));
    }
    float e0 = acc0 - X[(size_t)(r0 + warp*2    )*C_ + lane];
    float e1 = acc1 - X[(size_t)(r0 + warp*2 + 1)*C_ + lane];
    e_s[(warp*2    )*C_ + lane] = e0;
    e_s[(warp*2 + 1)*C_ + lane] = e1;
    float s2 = e0*e0 + e1*e1;
    #pragma unroll
    for (int off = 16; off > 0; off >>= 1) s2 += __shfl_down_sync(0xffffffffu, s2, off);
    if (lane == 0) red[warp] = s2;
    __syncthreads();   // publishes e_s for phase 4
    if (tid == 0) {
        float tot = 0.f;
        #pragma unroll
        for (int i = 0; i < 8; i++) tot += red[i];
        atomicAdd(&g_acc[0], tot);
    }

    // phase 3: S[f] partial (tid == f, conflict-free)
    {
        float ssum = 0.f;
        #pragma unroll
        for (int r = 0; r < 16; r++) ssum += hd_s[r*F_ + tid];
        atomicAdd(&g_S[tid], ssum);
    }

    // phase 4: G partial. warp owns f-block [warp*32, +32), lane = c.
    {
        int f0 = warp * 32;
        float ga[32];
        #pragma unroll
        for (int j = 0; j < 32; j++) ga[j] = 0.f;
        #pragma unroll 4
        for (int r = 0; r < 16; r++) {
            float ev = e_s[r*C_ + lane];
            #pragma unroll
            for (int j = 0; j < 8; j++) {
                float4 h4 = *(const float4*)&hd_s[r*F_ + f0 + j*4];
                ga[j*4+0] += ev * h4.x;
                ga[j*4+1] += ev * h4.y;
                ga[j*4+2] += ev * h4.z;
                ga[j*4+3] += ev * h4.w;
            }
        }
        float* gdst = &g_Gr[(blockIdx.x & (NREP-1))*C_*F_ + lane*F_ + f0];
        #pragma unroll
        for (int j = 0; j < 32; j++) atomicAdd(&gdst[j], ga[j]);
    }
}

// ---------------- final scalar assembly (1024 threads, shuffle reduce) -----
__global__ void final_kernel(const float* __restrict__ W, const float* __restrict__ w_d,
                             float* __restrict__ out) {
    __shared__ float4 red4[32];
    int tid = threadIdx.x, lane = tid & 31, warp = tid >> 5;

    float sG = 0.f, sWS = 0.f;
    #pragma unroll
    for (int i = tid; i < C_*F_; i += 1024) {
        float g = g_Gr[i] + g_Gr[C_*F_ + i] + g_Gr[2*C_*F_ + i] + g_Gr[3*C_*F_ + i];
        sG  += g * g;
        sWS += W[i] * g_S[i & 255] * w_d[i >> 8];
    }
    float sS  = (tid < F_) ? g_S[tid]*g_S[tid] : 0.f;
    float wd2 = (tid < C_) ? w_d[tid]*w_d[tid] : 0.f;

    #pragma unroll
    for (int off = 16; off > 0; off >>= 1) {
        sG  += __shfl_down_sync(0xffffffffu, sG,  off);
        sWS += __shfl_down_sync(0xffffffffu, sWS, off);
        sS  += __shfl_down_sync(0xffffffffu, sS,  off);
        wd2 += __shfl_down_sync(0xffffffffu, wd2, off);
    }
    if (lane == 0) red4[warp] = make_float4(sG, sWS, sS, wd2);
    __syncthreads();
    if (warp == 0) {
        float4 v = red4[lane];
        #pragma unroll
        for (int off = 16; off > 0; off >>= 1) {
            v.x += __shfl_down_sync(0xffffffffu, v.x, off);
            v.y += __shfl_down_sync(0xffffffffu, v.y, off);
            v.z += __shfl_down_sync(0xffffffffu, v.z, off);
            v.w += __shfl_down_sync(0xffffffffu, v.w, off);
        }
        if (lane == 0) {
            float loss_rec = g_acc[0] / 262144.f;                 // mean over B*T*C
            float loss_m   = 2.f * g_acc[1] / 1048576.f;          // 2*sum/(B*D*T)
            float normGrec = (2.f / 262144.f) * sqrtf(v.x);       // ||g_rec||_F
            float normGd   = sqrtf(v.w) * sqrtf(v.z) / 8192.f;    // ||g_d||_F (rank-1)
            float lmbda    = normGrec / (normGd + 1e-6f);
            float loss_d   = -v.y / 8192.f;
            out[0] = loss_rec + loss_m + lmbda * loss_d;
        }
    }
}

extern "C" void kernel_launch(void* const* d_in, const int* in_sizes, int n_in,
                              void* d_out, int out_size) {
    const float* X    = (const float*)d_in[0];
    const float* H    = (const float*)d_in[1];
    const float* M    = (const float*)d_in[2];
    const float* Hdec = (const float*)d_in[3];
    const float* W    = (const float*)d_in[4];
    const float* w_d  = (const float*)d_in[5];
    float* out = (float*)d_out;
    (void)in_sizes; (void)n_in; (void)out_size;

    static int attr_done = 0;
    if (!attr_done) {
        cudaFuncSetAttribute(nn4_kernel, cudaFuncAttributeMaxDynamicSharedMemorySize, 65536);
        cudaFuncSetAttribute(dec_kernel, cudaFuncAttributeMaxDynamicSharedMemorySize, 52224);
        attr_done = 1;
    }

    zero_kernel <<<(NREP*C_*F_ + 255)/256, 256>>>();
    nn4_kernel  <<<NQT*NKC, 256, 65536>>>(H, M);      // 2048 CTAs: the hot kernel
    nnred_kernel<<<Q_/256, 256>>>(H, M);
    dec_kernel  <<<Q_/16, 256, 52224>>>(Hdec, W, X);  // 512 CTAs
    final_kernel<<<1, 1024>>>(W, w_d, out);
}

// round 7
// speedup vs baseline: 1.7700x; 1.7700x over previous
#include <cuda_runtime.h>
#include <math.h>

#define B_ 8
#define T_ 1024
#define C_ 32
#define F_ 256
#define D_ 128
#define K_ 512
#define Q_ (B_*T_)      // 8192
#define KC 64
#define NKC (K_/KC)     // 8
#define QT 32
#define NQT (Q_/QT)     // 256
#define NREP 4          // G atomic replicas

// ---------------- scratch (no allocations allowed) ----------------
__device__ float g_bd[NKC*Q_];
__device__ int   g_bi[NKC*Q_];
__device__ float g_E[Q_*C_];
__device__ float g_Gr[NREP*C_*F_];
__device__ float g_S[F_];
__device__ float g_acc[2];   // [0] = sum E^2, [1] = sum (h-z)^2

__device__ __forceinline__ float2 fadd2(float2 a, float2 b) {
    float2 r;
    asm("add.rn.f32x2 %0, %1, %2;"
        : "=l"(reinterpret_cast<unsigned long long&>(r))
        : "l"(reinterpret_cast<unsigned long long&>(a)),
          "l"(reinterpret_cast<unsigned long long&>(b)));
    return r;
}

// ---------------- zero accumulators ----------------
__global__ void zero_kernel() {
    int g = blockIdx.x * 256 + threadIdx.x;
    if (g < NREP*C_*F_) g_Gr[g] = 0.f;
    if (g < F_)         g_S[g] = 0.f;
    if (g < 2)          g_acc[g] = 0.f;
}

// ---------------- L1 NN search (R3 config: packed diff, scalar abs-acc) ----
// 2048 CTAs (256 q-tiles x 8 k-chunks), 256 threads. CTA = 32 q x 64 k.
__global__ void nn3_kernel(const float* __restrict__ H, const float* __restrict__ M) {
    extern __shared__ char smem[];
    float2* h2_s = (float2*)smem;              // [128][32] (h,h)
    float*  m_s  = (float*)(smem + 32*1024);   // [128][64] negated

    int tid = threadIdx.x;
    int qt = blockIdx.x & (NQT - 1);
    int kc = blockIdx.x >> 8;
    int q0 = qt * QT;
    int b  = q0 >> 10;
    int t0 = q0 & (T_ - 1);
    int k0 = kc * KC;

    for (int e = tid; e < D_*QT; e += 256) {
        int d = e >> 5, q = e & 31;
        float v = H[b*(D_*T_) + d*T_ + t0 + q];
        h2_s[e] = make_float2(v, v);
    }
    for (int e = tid; e < (D_*KC)/4; e += 256) {
        int d = e >> 4, c4 = e & 15;
        float4 mv = *(const float4*)&M[d*K_ + k0 + c4*4];
        *(float4*)&m_s[d*KC + c4*4] = make_float4(-mv.x, -mv.y, -mv.z, -mv.w);
    }
    __syncthreads();

    int tk = tid & 15, tq = tid >> 4;
    int qq = tq * 2, kk = tk * 4;       // 16B-consecutive: conflict-free

    float d00=0.f,d01=0.f,d02=0.f,d03=0.f,d10=0.f,d11=0.f,d12=0.f,d13=0.f;
    #pragma unroll 4
    for (int d = 0; d < D_; d++) {
        float4 hh = *(const float4*)&h2_s[d*QT + qq];   // (h0,h0,h1,h1)
        float4 mm = *(const float4*)&m_s[d*KC + kk];    // (-k0,-k1,-k2,-k3)
        float2 t;
        t = fadd2(make_float2(hh.x, hh.y), make_float2(mm.x, mm.y));
        d00 += fabsf(t.x); d01 += fabsf(t.y);
        t = fadd2(make_float2(hh.x, hh.y), make_float2(mm.z, mm.w));
        d02 += fabsf(t.x); d03 += fabsf(t.y);
        t = fadd2(make_float2(hh.z, hh.w), make_float2(mm.x, mm.y));
        d10 += fabsf(t.x); d11 += fabsf(t.y);
        t = fadd2(make_float2(hh.z, hh.w), make_float2(mm.z, mm.w));
        d12 += fabsf(t.x); d13 += fabsf(t.y);
    }
    float bd0 = d00; int bi0 = k0 + kk;
    if (d01 < bd0) { bd0 = d01; bi0 = k0 + kk + 1; }
    if (d02 < bd0) { bd0 = d02; bi0 = k0 + kk + 2; }
    if (d03 < bd0) { bd0 = d03; bi0 = k0 + kk + 3; }
    float bd1 = d10; int bi1 = k0 + kk;
    if (d11 < bd1) { bd1 = d11; bi1 = k0 + kk + 1; }
    if (d12 < bd1) { bd1 = d12; bi1 = k0 + kk + 2; }
    if (d13 < bd1) { bd1 = d13; bi1 = k0 + kk + 3; }
    #pragma unroll
    for (int off = 1; off < 16; off <<= 1) {
        float od = __shfl_xor_sync(0xffffffffu, bd0, off);
        int   oi = __shfl_xor_sync(0xffffffffu, bi0, off);
        if (od < bd0 || (od == bd0 && oi < bi0)) { bd0 = od; bi0 = oi; }
        od = __shfl_xor_sync(0xffffffffu, bd1, off);
        oi = __shfl_xor_sync(0xffffffffu, bi1, off);
        if (od < bd1 || (od == bd1 && oi < bi1)) { bd1 = od; bi1 = oi; }
    }
    if (tk == 0) {
        g_bd[kc*Q_ + q0 + qq    ] = bd0;  g_bi[kc*Q_ + q0 + qq    ] = bi0;
        g_bd[kc*Q_ + q0 + qq + 1] = bd1;  g_bi[kc*Q_ + q0 + qq + 1] = bi1;
    }
}

// ---------------- combine K-chunks, compute sum (h - z)^2 ----------------
__global__ void nnred_kernel(const float* __restrict__ H, const float* __restrict__ M) {
    int tid = threadIdx.x;
    int q = blockIdx.x * 256 + tid;
    float bd = g_bd[q]; int bi = g_bi[q];
    #pragma unroll
    for (int c = 1; c < NKC; c++) {
        float dd = g_bd[c*Q_ + q]; int ii = g_bi[c*Q_ + q];
        if (dd < bd) { bd = dd; bi = ii; }   // chunks ascend in k
    }
    int b = q >> 10, t = q & (T_ - 1);
    const float* h = H + b*(D_*T_) + t;
    float s = 0.f;
    #pragma unroll 8
    for (int d = 0; d < D_; d++) {
        float diff = h[d*T_] - M[d*K_ + bi];
        s += diff * diff;
    }
    #pragma unroll
    for (int off = 16; off > 0; off >>= 1) s += __shfl_down_sync(0xffffffffu, s, off);
    __shared__ float red[8];
    int warp = tid >> 5, lane = tid & 31;
    if (lane == 0) red[warp] = s;
    __syncthreads();
    if (tid == 0) {
        float tot = 0.f;
        #pragma unroll
        for (int i = 0; i < 8; i++) tot += red[i];
        atomicAdd(&g_acc[1], tot);
    }
}

// ---------------- dec_e: E = Hdec W^T - X -> g_E (STG), sumE^2 -------------
// 512 CTAs x 256 threads, 16 rows each. One atomic per CTA.
__global__ void dece_kernel(const float* __restrict__ Hdec, const float* __restrict__ W,
                            const float* __restrict__ X) {
    extern __shared__ char smem[];
    float* hd_s = (float*)smem;                // [16][256]  16KB
    float* w_s  = (float*)(smem + 16384);      // [256][33]  33KB padded
    __shared__ float red[8];

    int tid = threadIdx.x;
    int r0 = blockIdx.x * 16;
    int warp = tid >> 5, lane = tid & 31;

    for (int e = tid; e < C_*F_; e += 256) {
        int c = e >> 8, f = e & 255;
        w_s[f*33 + c] = W[e];
    }
    {
        const float4* src = (const float4*)(Hdec + (size_t)r0 * F_);
        float4* dst = (float4*)hd_s;
        #pragma unroll
        for (int i = 0; i < 4; i++) dst[tid + i*256] = src[tid + i*256];
    }
    __syncthreads();

    float acc0 = 0.f, acc1 = 0.f;
    for (int f = 0; f < F_; f += 4) {
        float w0 = w_s[(f+0)*33 + lane];
        float w1 = w_s[(f+1)*33 + lane];
        float w2 = w_s[(f+2)*33 + lane];
        float w3 = w_s[(f+3)*33 + lane];
        float4 a4 = *(const float4*)&hd_s[(warp*2    )*F_ + f];   // broadcast
        float4 b4 = *(const float4*)&hd_s[(warp*2 + 1)*F_ + f];
        acc0 = fmaf(a4.x, w0, fmaf(a4.y, w1, fmaf(a4.z, w2, fmaf(a4.w, w3, acc0))));
        acc1 = fmaf(b4.x, w0, fmaf(b4.y, w1, fmaf(b4.z, w2, fmaf(b4.w, w3, acc1))));
    }
    float e0 = acc0 - X[(size_t)(r0 + warp*2    )*C_ + lane];
    float e1 = acc1 - X[(size_t)(r0 + warp*2 + 1)*C_ + lane];
    g_E[(r0 + warp*2    )*C_ + lane] = e0;      // coalesced STG
    g_E[(r0 + warp*2 + 1)*C_ + lane] = e1;
    float s2 = e0*e0 + e1*e1;
    #pragma unroll
    for (int off = 16; off > 0; off >>= 1) s2 += __shfl_down_sync(0xffffffffu, s2, off);
    if (lane == 0) red[warp] = s2;
    __syncthreads();
    if (tid == 0) {
        float tot = 0.f;
        #pragma unroll
        for (int i = 0; i < 8; i++) tot += red[i];
        atomicAdd(&g_acc[0], tot);
    }
}

// ---------------- dec_g: G = E^T @ Hdec (tiled GEMM) + S partials ----------
// 256 CTAs = 64 row-chunks (128 rows) x 4 f-tiles (64 f). 256 threads.
// Thread: 2 c x 4 f over 128 rows. Only 8 atomics/thread (524K total).
__global__ void decg_kernel(const float* __restrict__ Hdec) {
    __shared__ float e_s[64*32];    //  8KB
    __shared__ float hd_s[64*64];   // 16KB
    int tid = threadIdx.x;
    int rc = blockIdx.x & 63, ft = blockIdx.x >> 6;
    int r0 = rc * 128, f0 = ft * 64;
    int tc = tid & 15, tf = tid >> 4;     // c-pair, f-quad

    float ga[8] = {0,0,0,0,0,0,0,0};
    float scol = 0.f;                     // S partial for f = f0 + tid (tid < 64)

    for (int sub = 0; sub < 2; sub++) {
        int rr0 = r0 + sub*64;
        __syncthreads();
        {
            const float4* esrc = (const float4*)(g_E + (size_t)rr0 * C_);
            float4* edst = (float4*)e_s;
            edst[tid]       = esrc[tid];
            edst[tid + 256] = esrc[tid + 256];
            const float4* hsrc = (const float4*)(Hdec + (size_t)rr0 * F_ + f0);
            float4* hdst = (float4*)hd_s;
            #pragma unroll
            for (int i = 0; i < 4; i++) {
                int idx = tid + i*256;
                int row = idx >> 4, c4 = idx & 15;
                hdst[row*16 + c4] = hsrc[row*64 + c4];
            }
        }
        __syncthreads();
        #pragma unroll 4
        for (int r = 0; r < 64; r++) {
            float2 ec = *(const float2*)&e_s[r*32 + tc*2];
            float4 hv = *(const float4*)&hd_s[r*64 + tf*4];
            ga[0] += ec.x*hv.x; ga[1] += ec.x*hv.y; ga[2] += ec.x*hv.z; ga[3] += ec.x*hv.w;
            ga[4] += ec.y*hv.x; ga[5] += ec.y*hv.y; ga[6] += ec.y*hv.z; ga[7] += ec.y*hv.w;
        }
        if (tid < 64) {
            #pragma unroll 8
            for (int r = 0; r < 64; r++) scol += hd_s[r*64 + tid];
        }
    }

    if (tid < 64) atomicAdd(&g_S[f0 + tid], scol);
    float* gdst = &g_Gr[(rc & (NREP-1))*C_*F_];
    int c0 = tc*2, fbase = f0 + tf*4;
    #pragma unroll
    for (int j = 0; j < 4; j++) {
        atomicAdd(&gdst[(c0    )*F_ + fbase + j], ga[j]);
        atomicAdd(&gdst[(c0 + 1)*F_ + fbase + j], ga[4 + j]);
    }
}

// ---------------- final scalar assembly (1024 threads, shuffle reduce) -----
__global__ void final_kernel(const float* __restrict__ W, const float* __restrict__ w_d,
                             float* __restrict__ out) {
    __shared__ float4 red4[32];
    int tid = threadIdx.x, lane = tid & 31, warp = tid >> 5;

    float sG = 0.f, sWS = 0.f;
    #pragma unroll
    for (int i = tid; i < C_*F_; i += 1024) {
        float g = g_Gr[i] + g_Gr[C_*F_ + i] + g_Gr[2*C_*F_ + i] + g_Gr[3*C_*F_ + i];
        sG  += g * g;
        sWS += W[i] * g_S[i & 255] * w_d[i >> 8];
    }
    float sS  = (tid < F_) ? g_S[tid]*g_S[tid] : 0.f;
    float wd2 = (tid < C_) ? w_d[tid]*w_d[tid] : 0.f;

    #pragma unroll
    for (int off = 16; off > 0; off >>= 1) {
        sG  += __shfl_down_sync(0xffffffffu, sG,  off);
        sWS += __shfl_down_sync(0xffffffffu, sWS, off);
        sS  += __shfl_down_sync(0xffffffffu, sS,  off);
        wd2 += __shfl_down_sync(0xffffffffu, wd2, off);
    }
    if (lane == 0) red4[warp] = make_float4(sG, sWS, sS, wd2);
    __syncthreads();
    if (warp == 0) {
        float4 v = red4[lane];
        #pragma unroll
        for (int off = 16; off > 0; off >>= 1) {
            v.x += __shfl_down_sync(0xffffffffu, v.x, off);
            v.y += __shfl_down_sync(0xffffffffu, v.y, off);
            v.z += __shfl_down_sync(0xffffffffu, v.z, off);
            v.w += __shfl_down_sync(0xffffffffu, v.w, off);
        }
        if (lane == 0) {
            float loss_rec = g_acc[0] / 262144.f;                 // mean over B*T*C
            float loss_m   = 2.f * g_acc[1] / 1048576.f;          // 2*sum/(B*D*T)
            float normGrec = (2.f / 262144.f) * sqrtf(v.x);       // ||g_rec||_F
            float normGd   = sqrtf(v.w) * sqrtf(v.z) / 8192.f;    // ||g_d||_F (rank-1)
            float lmbda    = normGrec / (normGd + 1e-6f);
            float loss_d   = -v.y / 8192.f;
            out[0] = loss_rec + loss_m + lmbda * loss_d;
        }
    }
}

extern "C" void kernel_launch(void* const* d_in, const int* in_sizes, int n_in,
                              void* d_out, int out_size) {
    const float* X    = (const float*)d_in[0];
    const float* H    = (const float*)d_in[1];
    const float* M    = (const float*)d_in[2];
    const float* Hdec = (const float*)d_in[3];
    const float* W    = (const float*)d_in[4];
    const float* w_d  = (const float*)d_in[5];
    float* out = (float*)d_out;
    (void)in_sizes; (void)n_in; (void)out_size;

    static int attr_done = 0;
    if (!attr_done) {
        cudaFuncSetAttribute(nn3_kernel,  cudaFuncAttributeMaxDynamicSharedMemorySize, 65536);
        cudaFuncSetAttribute(dece_kernel, cudaFuncAttributeMaxDynamicSharedMemorySize, 50176);
        attr_done = 1;
    }

    zero_kernel <<<(NREP*C_*F_ + 255)/256, 256>>>();
    nn3_kernel  <<<NQT*NKC, 256, 65536>>>(H, M);       // 2048 CTAs: the hot kernel
    nnred_kernel<<<Q_/256, 256>>>(H, M);
    dece_kernel <<<Q_/16, 256, 50176>>>(Hdec, W, X);   // 512 CTAs
    decg_kernel <<<256, 256>>>(Hdec);                  // 256 CTAs
    final_kernel<<<1, 1024>>>(W, w_d, out);
}

// round 9
// speedup vs baseline: 2.1036x; 1.1885x over previous
#include <cuda_runtime.h>
#include <math.h>

#define B_ 8
#define T_ 1024
#define C_ 32
#define F_ 256
#define D_ 128
#define K_ 512
#define Q_ (B_*T_)      // 8192
#define KC 64
#define NKC (K_/KC)     // 8
#define QT 32
#define NQT (Q_/QT)     // 256
#define NREP 4          // G atomic replicas

// ---------------- scratch (no allocations allowed) ----------------
__device__ float g_bd[NKC*Q_];
__device__ int   g_bi[NKC*Q_];
__device__ float g_E[Q_*C_];
__device__ float g_Gr[NREP*C_*F_];
__device__ float g_S[F_];
__device__ float g_acc[2];   // [0] = sum E^2, [1] = sum (h-z)^2

__device__ __forceinline__ float2 fadd2(float2 a, float2 b) {
    float2 r;
    asm("add.rn.f32x2 %0, %1, %2;"
        : "=l"(reinterpret_cast<unsigned long long&>(r))
        : "l"(reinterpret_cast<unsigned long long&>(a)),
          "l"(reinterpret_cast<unsigned long long&>(b)));
    return r;
}

// ---------------- zero accumulators ----------------
__global__ void zero_kernel() {
    int g = blockIdx.x * 256 + threadIdx.x;
    if (g < NREP*C_*F_) g_Gr[g] = 0.f;
    if (g < F_)         g_S[g] = 0.f;
    if (g < 2)          g_acc[g] = 0.f;
}

// ---------------- L1 NN search (packed diff, scalar abs-acc) ---------------
// 2048 CTAs (256 q-tiles x 8 k-chunks), 256 threads. CTA = 32 q x 64 k.
__global__ void nn3_kernel(const float* __restrict__ H, const float* __restrict__ M) {
    extern __shared__ char smem[];
    float2* h2_s = (float2*)smem;              // [128][32] (h,h)
    float*  m_s  = (float*)(smem + 32*1024);   // [128][64] negated

    int tid = threadIdx.x;
    int qt = blockIdx.x & (NQT - 1);
    int kc = blockIdx.x >> 8;
    int q0 = qt * QT;
    int b  = q0 >> 10;
    int t0 = q0 & (T_ - 1);
    int k0 = kc * KC;

    for (int e = tid; e < D_*QT; e += 256) {
        int d = e >> 5, q = e & 31;
        float v = H[b*(D_*T_) + d*T_ + t0 + q];
        h2_s[e] = make_float2(v, v);
    }
    for (int e = tid; e < (D_*KC)/4; e += 256) {
        int d = e >> 4, c4 = e & 15;
        float4 mv = *(const float4*)&M[d*K_ + k0 + c4*4];
        *(float4*)&m_s[d*KC + c4*4] = make_float4(-mv.x, -mv.y, -mv.z, -mv.w);
    }
    __syncthreads();

    int tk = tid & 15, tq = tid >> 4;
    int qq = tq * 2, kk = tk * 4;       // 16B-consecutive: conflict-free

    float d00=0.f,d01=0.f,d02=0.f,d03=0.f,d10=0.f,d11=0.f,d12=0.f,d13=0.f;
    #pragma unroll 4
    for (int d = 0; d < D_; d++) {
        float4 hh = *(const float4*)&h2_s[d*QT + qq];   // (h0,h0,h1,h1)
        float4 mm = *(const float4*)&m_s[d*KC + kk];    // (-k0,-k1,-k2,-k3)
        float2 t;
        t = fadd2(make_float2(hh.x, hh.y), make_float2(mm.x, mm.y));
        d00 += fabsf(t.x); d01 += fabsf(t.y);
        t = fadd2(make_float2(hh.x, hh.y), make_float2(mm.z, mm.w));
        d02 += fabsf(t.x); d03 += fabsf(t.y);
        t = fadd2(make_float2(hh.z, hh.w), make_float2(mm.x, mm.y));
        d10 += fabsf(t.x); d11 += fabsf(t.y);
        t = fadd2(make_float2(hh.z, hh.w), make_float2(mm.z, mm.w));
        d12 += fabsf(t.x); d13 += fabsf(t.y);
    }
    float bd0 = d00; int bi0 = k0 + kk;
    if (d01 < bd0) { bd0 = d01; bi0 = k0 + kk + 1; }
    if (d02 < bd0) { bd0 = d02; bi0 = k0 + kk + 2; }
    if (d03 < bd0) { bd0 = d03; bi0 = k0 + kk + 3; }
    float bd1 = d10; int bi1 = k0 + kk;
    if (d11 < bd1) { bd1 = d11; bi1 = k0 + kk + 1; }
    if (d12 < bd1) { bd1 = d12; bi1 = k0 + kk + 2; }
    if (d13 < bd1) { bd1 = d13; bi1 = k0 + kk + 3; }
    #pragma unroll
    for (int off = 1; off < 16; off <<= 1) {
        float od = __shfl_xor_sync(0xffffffffu, bd0, off);
        int   oi = __shfl_xor_sync(0xffffffffu, bi0, off);
        if (od < bd0 || (od == bd0 && oi < bi0)) { bd0 = od; bi0 = oi; }
        od = __shfl_xor_sync(0xffffffffu, bd1, off);
        oi = __shfl_xor_sync(0xffffffffu, bi1, off);
        if (od < bd1 || (od == bd1 && oi < bi1)) { bd1 = od; bi1 = oi; }
    }
    if (tk == 0) {
        g_bd[kc*Q_ + q0 + qq    ] = bd0;  g_bi[kc*Q_ + q0 + qq    ] = bi0;
        g_bd[kc*Q_ + q0 + qq + 1] = bd1;  g_bi[kc*Q_ + q0 + qq + 1] = bi1;
    }
}

// ---------------- combine K-chunks, compute sum (h - z)^2 ----------------
__global__ void nnred_kernel(const float* __restrict__ H, const float* __restrict__ M) {
    int tid = threadIdx.x;
    int q = blockIdx.x * 256 + tid;
    float bd = g_bd[q]; int bi = g_bi[q];
    #pragma unroll
    for (int c = 1; c < NKC; c++) {
        float dd = g_bd[c*Q_ + q]; int ii = g_bi[c*Q_ + q];
        if (dd < bd) { bd = dd; bi = ii; }   // chunks ascend in k
    }
    int b = q >> 10, t = q & (T_ - 1);
    const float* h = H + b*(D_*T_) + t;
    float s = 0.f;
    #pragma unroll 8
    for (int d = 0; d < D_; d++) {
        float diff = h[d*T_] - M[d*K_ + bi];
        s += diff * diff;
    }
    #pragma unroll
    for (int off = 16; off > 0; off >>= 1) s += __shfl_down_sync(0xffffffffu, s, off);
    __shared__ float red[8];
    int warp = tid >> 5, lane = tid & 31;
    if (lane == 0) red[warp] = s;
    __syncthreads();
    if (tid == 0) {
        float tot = 0.f;
        #pragma unroll
        for (int i = 0; i < 8; i++) tot += red[i];
        atomicAdd(&g_acc[1], tot);
    }
}

// ---------------- dec_e: E = Hdec W^T - X -> g_E (STG), sumE^2 -------------
// 512 CTAs x 256 threads, 16 rows each. One atomic per CTA.
__global__ void dece_kernel(const float* __restrict__ Hdec, const float* __restrict__ W,
                            const float* __restrict__ X) {
    extern __shared__ char smem[];
    float* hd_s = (float*)smem;                // [16][256]  16KB
    float* w_s  = (float*)(smem + 16384);      // [256][33]  33KB padded
    __shared__ float red[8];

    int tid = threadIdx.x;
    int r0 = blockIdx.x * 16;
    int warp = tid >> 5, lane = tid & 31;

    for (int e = tid; e < C_*F_; e += 256) {
        int c = e >> 8, f = e & 255;
        w_s[f*33 + c] = W[e];
    }
    {
        const float4* src = (const float4*)(Hdec + (size_t)r0 * F_);
        float4* dst = (float4*)hd_s;
        #pragma unroll
        for (int i = 0; i < 4; i++) dst[tid + i*256] = src[tid + i*256];
    }
    __syncthreads();

    float acc0 = 0.f, acc1 = 0.f;
    for (int f = 0; f < F_; f += 4) {
        float w0 = w_s[(f+0)*33 + lane];
        float w1 = w_s[(f+1)*33 + lane];
        float w2 = w_s[(f+2)*33 + lane];
        float w3 = w_s[(f+3)*33 + lane];
        float4 a4 = *(const float4*)&hd_s[(warp*2    )*F_ + f];   // broadcast
        float4 b4 = *(const float4*)&hd_s[(warp*2 + 1)*F_ + f];
        acc0 = fmaf(a4.x, w0, fmaf(a4.y, w1, fmaf(a4.z, w2, fmaf(a4.w, w3, acc0))));
        acc1 = fmaf(b4.x, w0, fmaf(b4.y, w1, fmaf(b4.z, w2, fmaf(b4.w, w3, acc1))));
    }
    float e0 = acc0 - X[(size_t)(r0 + warp*2    )*C_ + lane];
    float e1 = acc1 - X[(size_t)(r0 + warp*2 + 1)*C_ + lane];
    g_E[(r0 + warp*2    )*C_ + lane] = e0;      // coalesced STG
    g_E[(r0 + warp*2 + 1)*C_ + lane] = e1;
    float s2 = e0*e0 + e1*e1;
    #pragma unroll
    for (int off = 16; off > 0; off >>= 1) s2 += __shfl_down_sync(0xffffffffu, s2, off);
    if (lane == 0) red[warp] = s2;
    __syncthreads();
    if (tid == 0) {
        float tot = 0.f;
        #pragma unroll
        for (int i = 0; i < 8; i++) tot += red[i];
        atomicAdd(&g_acc[0], tot);
    }
}

// ---------------- dec_g: G = E^T @ Hdec (tiled GEMM) + S partials ----------
// 256 CTAs = 64 row-chunks (128 rows) x 4 f-tiles (64 f). 256 threads.
__global__ void decg_kernel(const float* __restrict__ Hdec) {
    __shared__ float e_s[64*32];    //  8KB
    __shared__ float hd_s[64*64];   // 16KB
    int tid = threadIdx.x;
    int rc = blockIdx.x & 63, ft = blockIdx.x >> 6;
    int r0 = rc * 128, f0 = ft * 64;
    int tc = tid & 15, tf = tid >> 4;     // c-pair, f-quad

    float ga[8] = {0,0,0,0,0,0,0,0};
    float scol = 0.f;                     // S partial for f = f0 + tid (tid < 64)

    for (int sub = 0; sub < 2; sub++) {
        int rr0 = r0 + sub*64;
        __syncthreads();
        {
            const float4* esrc = (const float4*)(g_E + (size_t)rr0 * C_);
            float4* edst = (float4*)e_s;
            edst[tid]       = esrc[tid];
            edst[tid + 256] = esrc[tid + 256];
            const float4* hsrc = (const float4*)(Hdec + (size_t)rr0 * F_ + f0);
            float4* hdst = (float4*)hd_s;
            #pragma unroll
            for (int i = 0; i < 4; i++) {
                int idx = tid + i*256;
                int row = idx >> 4, c4 = idx & 15;
                hdst[row*16 + c4] = hsrc[row*64 + c4];
            }
        }
        __syncthreads();
        #pragma unroll 4
        for (int r = 0; r < 64; r++) {
            float2 ec = *(const float2*)&e_s[r*32 + tc*2];
            float4 hv = *(const float4*)&hd_s[r*64 + tf*4];
            ga[0] += ec.x*hv.x; ga[1] += ec.x*hv.y; ga[2] += ec.x*hv.z; ga[3] += ec.x*hv.w;
            ga[4] += ec.y*hv.x; ga[5] += ec.y*hv.y; ga[6] += ec.y*hv.z; ga[7] += ec.y*hv.w;
        }
        if (tid < 64) {
            #pragma unroll 8
            for (int r = 0; r < 64; r++) scol += hd_s[r*64 + tid];
        }
    }

    if (tid < 64) atomicAdd(&g_S[f0 + tid], scol);
    float* gdst = &g_Gr[(rc & (NREP-1))*C_*F_];
    int c0 = tc*2, fbase = f0 + tf*4;
    #pragma unroll
    for (int j = 0; j < 4; j++) {
        atomicAdd(&gdst[(c0    )*F_ + fbase + j], ga[j]);
        atomicAdd(&gdst[(c0 + 1)*F_ + fbase + j], ga[4 + j]);
    }
}

// ---------------- final scalar assembly (1024 threads, shuffle reduce) -----
__global__ void final_kernel(const float* __restrict__ W, const float* __restrict__ w_d,
                             float* __restrict__ out) {
    __shared__ float4 red4[32];
    int tid = threadIdx.x, lane = tid & 31, warp = tid >> 5;

    float sG = 0.f, sWS = 0.f;
    #pragma unroll
    for (int i = tid; i < C_*F_; i += 1024) {
        float g = g_Gr[i] + g_Gr[C_*F_ + i] + g_Gr[2*C_*F_ + i] + g_Gr[3*C_*F_ + i];
        sG  += g * g;
        sWS += W[i] * g_S[i & 255] * w_d[i >> 8];
    }
    float sS  = (tid < F_) ? g_S[tid]*g_S[tid] : 0.f;
    float wd2 = (tid < C_) ? w_d[tid]*w_d[tid] : 0.f;

    #pragma unroll
    for (int off = 16; off > 0; off >>= 1) {
        sG  += __shfl_down_sync(0xffffffffu, sG,  off);
        sWS += __shfl_down_sync(0xffffffffu, sWS, off);
        sS  += __shfl_down_sync(0xffffffffu, sS,  off);
        wd2 += __shfl_down_sync(0xffffffffu, wd2, off);
    }
    if (lane == 0) red4[warp] = make_float4(sG, sWS, sS, wd2);
    __syncthreads();
    if (warp == 0) {
        float4 v = red4[lane];
        #pragma unroll
        for (int off = 16; off > 0; off >>= 1) {
            v.x += __shfl_down_sync(0xffffffffu, v.x, off);
            v.y += __shfl_down_sync(0xffffffffu, v.y, off);
            v.z += __shfl_down_sync(0xffffffffu, v.z, off);
            v.w += __shfl_down_sync(0xffffffffu, v.w, off);
        }
        if (lane == 0) {
            float loss_rec = g_acc[0] / 262144.f;                 // mean over B*T*C
            float loss_m   = 2.f * g_acc[1] / 1048576.f;          // 2*sum/(B*D*T)
            float normGrec = (2.f / 262144.f) * sqrtf(v.x);       // ||g_rec||_F
            float normGd   = sqrtf(v.w) * sqrtf(v.z) / 8192.f;    // ||g_d||_F (rank-1)
            float lmbda    = normGrec / (normGd + 1e-6f);
            float loss_d   = -v.y / 8192.f;
            out[0] = loss_rec + loss_m + lmbda * loss_d;
        }
    }
}

extern "C" void kernel_launch(void* const* d_in, const int* in_sizes, int n_in,
                              void* d_out, int out_size) {
    const float* X    = (const float*)d_in[0];
    const float* H    = (const float*)d_in[1];
    const float* M    = (const float*)d_in[2];
    const float* Hdec = (const float*)d_in[3];
    const float* W    = (const float*)d_in[4];
    const float* w_d  = (const float*)d_in[5];
    float* out = (float*)d_out;
    (void)in_sizes; (void)n_in; (void)out_size;

    static int init_done = 0;
    static cudaStream_t s2;
    static cudaEvent_t ev_fork, ev_join;
    if (!init_done) {
        cudaFuncSetAttribute(nn3_kernel,  cudaFuncAttributeMaxDynamicSharedMemorySize, 65536);
        cudaFuncSetAttribute(dece_kernel, cudaFuncAttributeMaxDynamicSharedMemorySize, 50176);
        cudaStreamCreateWithFlags(&s2, cudaStreamNonBlocking);
        cudaEventCreateWithFlags(&ev_fork, cudaEventDisableTiming);
        cudaEventCreateWithFlags(&ev_join, cudaEventDisableTiming);
        init_done = 1;
    }

    // fork: decoder chain on s2 runs concurrently with the NN chain on the
    // capture (default) stream; both join before final_kernel.
    cudaEventRecord(ev_fork, 0);
    cudaStreamWaitEvent(s2, ev_fork, 0);

    // s2 chain (independent of H/M): zero -> E -> G/S
    zero_kernel <<<(NREP*C_*F_ + 255)/256, 256, 0, s2>>>();
    dece_kernel <<<Q_/16, 256, 50176, s2>>>(Hdec, W, X);   // 512 CTAs
    decg_kernel <<<256, 256, 0, s2>>>(Hdec);               // 256 CTAs

    // main chain: the hot NN search
    nn3_kernel  <<<NQT*NKC, 256, 65536>>>(H, M);           // 2048 CTAs
    nnred_kernel<<<Q_/256, 256>>>(H, M);

    // join
    cudaEventRecord(ev_join, s2);
    cudaStreamWaitEvent(0, ev_join, 0);
    final_kernel<<<1, 1024>>>(W, w_d, out);
}

// round 10
// speedup vs baseline: 2.1646x; 1.0290x over previous
#include <cuda_runtime.h>
#include <math.h>

#define B_ 8
#define T_ 1024
#define C_ 32
#define F_ 256
#define D_ 128
#define K_ 512
#define Q_ (B_*T_)      // 8192
#define KCH 128         // k per CTA chunk
#define NKC (K_/KCH)    // 4
#define QT 32
#define NQT (Q_/QT)     // 256
#define NREP 4          // G atomic replicas

// ---------------- scratch (no allocations allowed) ----------------
__device__ float g_bd[NKC*Q_];
__device__ int   g_bi[NKC*Q_];
__device__ float g_E[Q_*C_];
__device__ float g_Gr[NREP*C_*F_];
__device__ float g_S[F_];
__device__ float g_acc[2];   // [0] = sum E^2, [1] = sum (h-z)^2

#define ABSMASK 0x7fffffff7fffffffULL

__device__ __forceinline__ unsigned long long fadd2u(unsigned long long a,
                                                     unsigned long long b) {
    unsigned long long r;
    asm("add.rn.f32x2 %0, %1, %2;" : "=l"(r) : "l"(a), "l"(b));
    return r;
}

// ---------------- zero accumulators ----------------
__global__ void zero_kernel() {
    int g = blockIdx.x * 256 + threadIdx.x;
    if (g < NREP*C_*F_) g_Gr[g] = 0.f;
    if (g < F_)         g_S[g] = 0.f;
    if (g < 2)          g_acc[g] = 0.f;
}

// ---------------- L1 NN search: packed diff/abs/acc, 8 u64 chains ----------
// 1024 CTAs (256 q-tiles x 4 k-chunks), 256 threads. CTA = 32 q x 128 k.
// Thread tile 2q x 8k: two conflict-free 4k groups at kk and kk+64.
// Per d: 8 fadd2 diff (fma) + 8 u64 AND (16 LOP3, alu) + 8 fadd2 acc (fma)
//   -> 1.0 fma + 1.0 alu instr per element, 3 smem bytes per element.
__global__ void nn5_kernel(const float* __restrict__ H, const float* __restrict__ M) {
    extern __shared__ char smem[];
    float2* h2_s = (float2*)smem;              // [128][32] (h,h) duplicated, 32KB
    float*  m_s  = (float*)(smem + 32*1024);   // [128][128] negated, 64KB

    int tid = threadIdx.x;
    int qt = blockIdx.x & (NQT - 1);
    int kc = blockIdx.x >> 8;
    int q0 = qt * QT;
    int b  = q0 >> 10;
    int t0 = q0 & (T_ - 1);
    int k0 = kc * KCH;

    for (int e = tid; e < D_*QT; e += 256) {
        int d = e >> 5, q = e & 31;
        float v = H[b*(D_*T_) + d*T_ + t0 + q];
        h2_s[e] = make_float2(v, v);
    }
    for (int e = tid; e < (D_*KCH)/4; e += 256) {
        int d = e >> 5, c4 = e & 31;
        float4 mv = *(const float4*)&M[d*K_ + k0 + c4*4];
        *(float4*)&m_s[d*KCH + c4*4] = make_float4(-mv.x, -mv.y, -mv.z, -mv.w);
    }
    __syncthreads();

    int tk = tid & 15, tq = tid >> 4;   // 16 k-groups x 16 q-groups
    int qq = tq * 2, kk = tk * 4;       // both m groups 16B-consecutive: conflict-free

    unsigned long long aA0=0ULL,aA1=0ULL,aA2=0ULL,aA3=0ULL;
    unsigned long long aB0=0ULL,aB1=0ULL,aB2=0ULL,aB3=0ULL;
    #pragma unroll 4
    for (int d = 0; d < D_; d++) {
        ulonglong2 hh = *(const ulonglong2*)&h2_s[d*QT + qq];        // (h0,h0),(h1,h1)
        ulonglong2 mA = *(const ulonglong2*)&m_s[d*KCH + kk];        // group A: k kk..kk+3
        ulonglong2 mB = *(const ulonglong2*)&m_s[d*KCH + 64 + kk];   // group B: k 64+kk..
        aA0 = fadd2u(aA0, fadd2u(hh.x, mA.x) & ABSMASK);
        aA1 = fadd2u(aA1, fadd2u(hh.x, mA.y) & ABSMASK);
        aA2 = fadd2u(aA2, fadd2u(hh.y, mA.x) & ABSMASK);
        aA3 = fadd2u(aA3, fadd2u(hh.y, mA.y) & ABSMASK);
        aB0 = fadd2u(aB0, fadd2u(hh.x, mB.x) & ABSMASK);
        aB1 = fadd2u(aB1, fadd2u(hh.x, mB.y) & ABSMASK);
        aB2 = fadd2u(aB2, fadd2u(hh.y, mB.x) & ABSMASK);
        aB3 = fadd2u(aB3, fadd2u(hh.y, mB.y) & ABSMASK);
    }

    // thread-local lexmin, ascending k (strict < keeps lowest index)
    int kbA = k0 + kk, kbB = k0 + 64 + kk;
    float bd0, bd1; int bi0, bi1;
    {
        unsigned long long pq[4] = {aA0, aA1, aB0, aB1};
        int bases[4] = {kbA, kbA + 2, kbB, kbB + 2};
        bd0 = 3.4e38f; bi0 = 0;
        #pragma unroll
        for (int j = 0; j < 4; j++) {
            float lo = __uint_as_float((unsigned)(pq[j] & 0xffffffffu));
            float hi = __uint_as_float((unsigned)(pq[j] >> 32));
            if (lo < bd0) { bd0 = lo; bi0 = bases[j]; }
            if (hi < bd0) { bd0 = hi; bi0 = bases[j] + 1; }
        }
    }
    {
        unsigned long long pq[4] = {aA2, aA3, aB2, aB3};
        int bases[4] = {kbA, kbA + 2, kbB, kbB + 2};
        bd1 = 3.4e38f; bi1 = 0;
        #pragma unroll
        for (int j = 0; j < 4; j++) {
            float lo = __uint_as_float((unsigned)(pq[j] & 0xffffffffu));
            float hi = __uint_as_float((unsigned)(pq[j] >> 32));
            if (lo < bd1) { bd1 = lo; bi1 = bases[j]; }
            if (hi < bd1) { bd1 = hi; bi1 = bases[j] + 1; }
        }
    }

    // lexicographic min across the 16 tk lanes (first-argmin semantics)
    #pragma unroll
    for (int off = 1; off < 16; off <<= 1) {
        float od = __shfl_xor_sync(0xffffffffu, bd0, off);
        int   oi = __shfl_xor_sync(0xffffffffu, bi0, off);
        if (od < bd0 || (od == bd0 && oi < bi0)) { bd0 = od; bi0 = oi; }
        od = __shfl_xor_sync(0xffffffffu, bd1, off);
        oi = __shfl_xor_sync(0xffffffffu, bi1, off);
        if (od < bd1 || (od == bd1 && oi < bi1)) { bd1 = od; bi1 = oi; }
    }
    if (tk == 0) {
        g_bd[kc*Q_ + q0 + qq    ] = bd0;  g_bi[kc*Q_ + q0 + qq    ] = bi0;
        g_bd[kc*Q_ + q0 + qq + 1] = bd1;  g_bi[kc*Q_ + q0 + qq + 1] = bi1;
    }
}

// ---------------- combine K-chunks, compute sum (h - z)^2 ----------------
__global__ void nnred_kernel(const float* __restrict__ H, const float* __restrict__ M) {
    int tid = threadIdx.x;
    int q = blockIdx.x * 256 + tid;
    float bd = g_bd[q]; int bi = g_bi[q];
    #pragma unroll
    for (int c = 1; c < NKC; c++) {
        float dd = g_bd[c*Q_ + q]; int ii = g_bi[c*Q_ + q];
        if (dd < bd) { bd = dd; bi = ii; }   // chunks ascend in k
    }
    int b = q >> 10, t = q & (T_ - 1);
    const float* h = H + b*(D_*T_) + t;
    float s = 0.f;
    #pragma unroll 8
    for (int d = 0; d < D_; d++) {
        float diff = h[d*T_] - M[d*K_ + bi];
        s += diff * diff;
    }
    #pragma unroll
    for (int off = 16; off > 0; off >>= 1) s += __shfl_down_sync(0xffffffffu, s, off);
    __shared__ float red[8];
    int warp = tid >> 5, lane = tid & 31;
    if (lane == 0) red[warp] = s;
    __syncthreads();
    if (tid == 0) {
        float tot = 0.f;
        #pragma unroll
        for (int i = 0; i < 8; i++) tot += red[i];
        atomicAdd(&g_acc[1], tot);
    }
}

// ---------------- dec_e: E = Hdec W^T - X -> g_E (STG), sumE^2 -------------
__global__ void dece_kernel(const float* __restrict__ Hdec, const float* __restrict__ W,
                            const float* __restrict__ X) {
    extern __shared__ char smem[];
    float* hd_s = (float*)smem;                // [16][256]  16KB
    float* w_s  = (float*)(smem + 16384);      // [256][33]  33KB padded
    __shared__ float red[8];

    int tid = threadIdx.x;
    int r0 = blockIdx.x * 16;
    int warp = tid >> 5, lane = tid & 31;

    for (int e = tid; e < C_*F_; e += 256) {
        int c = e >> 8, f = e & 255;
        w_s[f*33 + c] = W[e];
    }
    {
        const float4* src = (const float4*)(Hdec + (size_t)r0 * F_);
        float4* dst = (float4*)hd_s;
        #pragma unroll
        for (int i = 0; i < 4; i++) dst[tid + i*256] = src[tid + i*256];
    }
    __syncthreads();

    float acc0 = 0.f, acc1 = 0.f;
    for (int f = 0; f < F_; f += 4) {
        float w0 = w_s[(f+0)*33 + lane];
        float w1 = w_s[(f+1)*33 + lane];
        float w2 = w_s[(f+2)*33 + lane];
        float w3 = w_s[(f+3)*33 + lane];
        float4 a4 = *(const float4*)&hd_s[(warp*2    )*F_ + f];
        float4 b4 = *(const float4*)&hd_s[(warp*2 + 1)*F_ + f];
        acc0 = fmaf(a4.x, w0, fmaf(a4.y, w1, fmaf(a4.z, w2, fmaf(a4.w, w3, acc0))));
        acc1 = fmaf(b4.x, w0, fmaf(b4.y, w1, fmaf(b4.z, w2, fmaf(b4.w, w3, acc1))));
    }
    float e0 = acc0 - X[(size_t)(r0 + warp*2    )*C_ + lane];
    float e1 = acc1 - X[(size_t)(r0 + warp*2 + 1)*C_ + lane];
    g_E[(r0 + warp*2    )*C_ + lane] = e0;
    g_E[(r0 + warp*2 + 1)*C_ + lane] = e1;
    float s2 = e0*e0 + e1*e1;
    #pragma unroll
    for (int off = 16; off > 0; off >>= 1) s2 += __shfl_down_sync(0xffffffffu, s2, off);
    if (lane == 0) red[warp] = s2;
    __syncthreads();
    if (tid == 0) {
        float tot = 0.f;
        #pragma unroll
        for (int i = 0; i < 8; i++) tot += red[i];
        atomicAdd(&g_acc[0], tot);
    }
}

// ---------------- dec_g: G = E^T @ Hdec (tiled GEMM) + S partials ----------
__global__ void decg_kernel(const float* __restrict__ Hdec) {
    __shared__ float e_s[64*32];    //  8KB
    __shared__ float hd_s[64*64];   // 16KB
    int tid = threadIdx.x;
    int rc = blockIdx.x & 63, ft = blockIdx.x >> 6;
    int r0 = rc * 128, f0 = ft * 64;
    int tc = tid & 15, tf = tid >> 4;

    float ga[8] = {0,0,0,0,0,0,0,0};
    float scol = 0.f;

    for (int sub = 0; sub < 2; sub++) {
        int rr0 = r0 + sub*64;
        __syncthreads();
        {
            const float4* esrc = (const float4*)(g_E + (size_t)rr0 * C_);
            float4* edst = (float4*)e_s;
            edst[tid]       = esrc[tid];
            edst[tid + 256] = esrc[tid + 256];
            const float4* hsrc = (const float4*)(Hdec + (size_t)rr0 * F_ + f0);
            float4* hdst = (float4*)hd_s;
            #pragma unroll
            for (int i = 0; i < 4; i++) {
                int idx = tid + i*256;
                int row = idx >> 4, c4 = idx & 15;
                hdst[row*16 + c4] = hsrc[row*64 + c4];
            }
        }
        __syncthreads();
        #pragma unroll 4
        for (int r = 0; r < 64; r++) {
            float2 ec = *(const float2*)&e_s[r*32 + tc*2];
            float4 hv = *(const float4*)&hd_s[r*64 + tf*4];
            ga[0] += ec.x*hv.x; ga[1] += ec.x*hv.y; ga[2] += ec.x*hv.z; ga[3] += ec.x*hv.w;
            ga[4] += ec.y*hv.x; ga[5] += ec.y*hv.y; ga[6] += ec.y*hv.z; ga[7] += ec.y*hv.w;
        }
        if (tid < 64) {
            #pragma unroll 8
            for (int r = 0; r < 64; r++) scol += hd_s[r*64 + tid];
        }
    }

    if (tid < 64) atomicAdd(&g_S[f0 + tid], scol);
    float* gdst = &g_Gr[(rc & (NREP-1))*C_*F_];
    int c0 = tc*2, fbase = f0 + tf*4;
    #pragma unroll
    for (int j = 0; j < 4; j++) {
        atomicAdd(&gdst[(c0    )*F_ + fbase + j], ga[j]);
        atomicAdd(&gdst[(c0 + 1)*F_ + fbase + j], ga[4 + j]);
    }
}

// ---------------- final scalar assembly (1024 threads, shuffle reduce) -----
__global__ void final_kernel(const float* __restrict__ W, const float* __restrict__ w_d,
                             float* __restrict__ out) {
    __shared__ float4 red4[32];
    int tid = threadIdx.x, lane = tid & 31, warp = tid >> 5;

    float sG = 0.f, sWS = 0.f;
    #pragma unroll
    for (int i = tid; i < C_*F_; i += 1024) {
        float g = g_Gr[i] + g_Gr[C_*F_ + i] + g_Gr[2*C_*F_ + i] + g_Gr[3*C_*F_ + i];
        sG  += g * g;
        sWS += W[i] * g_S[i & 255] * w_d[i >> 8];
    }
    float sS  = (tid < F_) ? g_S[tid]*g_S[tid] : 0.f;
    float wd2 = (tid < C_) ? w_d[tid]*w_d[tid] : 0.f;

    #pragma unroll
    for (int off = 16; off > 0; off >>= 1) {
        sG  += __shfl_down_sync(0xffffffffu, sG,  off);
        sWS += __shfl_down_sync(0xffffffffu, sWS, off);
        sS  += __shfl_down_sync(0xffffffffu, sS,  off);
        wd2 += __shfl_down_sync(0xffffffffu, wd2, off);
    }
    if (lane == 0) red4[warp] = make_float4(sG, sWS, sS, wd2);
    __syncthreads();
    if (warp == 0) {
        float4 v = red4[lane];
        #pragma unroll
        for (int off = 16; off > 0; off >>= 1) {
            v.x += __shfl_down_sync(0xffffffffu, v.x, off);
            v.y += __shfl_down_sync(0xffffffffu, v.y, off);
            v.z += __shfl_down_sync(0xffffffffu, v.z, off);
            v.w += __shfl_down_sync(0xffffffffu, v.w, off);
        }
        if (lane == 0) {
            float loss_rec = g_acc[0] / 262144.f;                 // mean over B*T*C
            float loss_m   = 2.f * g_acc[1] / 1048576.f;          // 2*sum/(B*D*T)
            float normGrec = (2.f / 262144.f) * sqrtf(v.x);       // ||g_rec||_F
            float normGd   = sqrtf(v.w) * sqrtf(v.z) / 8192.f;    // ||g_d||_F (rank-1)
            float lmbda    = normGrec / (normGd + 1e-6f);
            float loss_d   = -v.y / 8192.f;
            out[0] = loss_rec + loss_m + lmbda * loss_d;
        }
    }
}

extern "C" void kernel_launch(void* const* d_in, const int* in_sizes, int n_in,
                              void* d_out, int out_size) {
    const float* X    = (const float*)d_in[0];
    const float* H    = (const float*)d_in[1];
    const float* M    = (const float*)d_in[2];
    const float* Hdec = (const float*)d_in[3];
    const float* W    = (const float*)d_in[4];
    const float* w_d  = (const float*)d_in[5];
    float* out = (float*)d_out;
    (void)in_sizes; (void)n_in; (void)out_size;

    static int init_done = 0;
    static cudaStream_t s2;
    static cudaEvent_t ev_fork, ev_join;
    if (!init_done) {
        cudaFuncSetAttribute(nn5_kernel,  cudaFuncAttributeMaxDynamicSharedMemorySize, 98304);
        cudaFuncSetAttribute(dece_kernel, cudaFuncAttributeMaxDynamicSharedMemorySize, 50176);
        cudaStreamCreateWithFlags(&s2, cudaStreamNonBlocking);
        cudaEventCreateWithFlags(&ev_fork, cudaEventDisableTiming);
        cudaEventCreateWithFlags(&ev_join, cudaEventDisableTiming);
        init_done = 1;
    }

    // fork: decoder chain on s2 overlaps the NN chain on the capture stream
    cudaEventRecord(ev_fork, 0);
    cudaStreamWaitEvent(s2, ev_fork, 0);

    zero_kernel <<<(NREP*C_*F_ + 255)/256, 256, 0, s2>>>();
    dece_kernel <<<Q_/16, 256, 50176, s2>>>(Hdec, W, X);   // 512 CTAs
    decg_kernel <<<256, 256, 0, s2>>>(Hdec);               // 256 CTAs

    nn5_kernel  <<<NQT*NKC, 256, 98304>>>(H, M);           // 1024 CTAs: hot kernel
    nnred_kernel<<<Q_/256, 256>>>(H, M);

    cudaEventRecord(ev_join, s2);
    cudaStreamWaitEvent(0, ev_join, 0);
    final_kernel<<<1, 1024>>>(W, w_d, out);
}

// round 11
// speedup vs baseline: 2.4972x; 1.1537x over previous
#include <cuda_runtime.h>
#include <math.h>

#define B_ 8
#define T_ 1024
#define C_ 32
#define F_ 256
#define D_ 128
#define K_ 512
#define Q_ (B_*T_)      // 8192
#define KCH 64          // k per CTA chunk
#define NKC (K_/KCH)    // 8
#define QT 64
#define NQT (Q_/QT)     // 128
#define NREP 4          // G atomic replicas

// ---------------- scratch (no allocations allowed) ----------------
__device__ float g_bd[NKC*Q_];
__device__ int   g_bi[NKC*Q_];
__device__ float g_E[Q_*C_];
__device__ float g_Gr[NREP*C_*F_];
__device__ float g_S[F_];
__device__ float g_acc[2];   // [0] = sum E^2, [1] = sum (h-z)^2

#define ABSMASK 0x7fffffff7fffffffULL

__device__ __forceinline__ unsigned long long fadd2u(unsigned long long a,
                                                     unsigned long long b) {
    unsigned long long r;
    asm("add.rn.f32x2 %0, %1, %2;" : "=l"(r) : "l"(a), "l"(b));
    return r;
}

__device__ __forceinline__ unsigned long long dupf(float v) {
    float2 p = make_float2(v, v);
    return reinterpret_cast<unsigned long long&>(p);
}

// ---------------- zero accumulators ----------------
__global__ void zero_kernel() {
    int g = blockIdx.x * 256 + threadIdx.x;
    if (g < NREP*C_*F_) g_Gr[g] = 0.f;
    if (g < F_)         g_S[g] = 0.f;
    if (g < 2)          g_acc[g] = 0.f;
}

// ---------------- L1 NN search: 4q x 4k tile, reg-dup h, packed everything -
// 1024 CTAs (128 q-tiles x 8 k-chunks), 256 threads. CTA = 64 q x 64 k.
// smem: h plain [128][64] 32KB + m negated [128][64] 32KB = 64KB -> 3 CTA/SM.
// Per d per thread: 2 LDS.128 + 4 MOV + 8 fadd2 diff + 8 u64 AND + 8 fadd2 acc
//   = fma 1.0 / alu 1.25 / issue 2.375 per element.
__global__ void nn6_kernel(const float* __restrict__ H, const float* __restrict__ M) {
    extern __shared__ char smem[];
    float* h_s = (float*)smem;                 // [128][64] plain
    float* m_s = (float*)(smem + 32*1024);     // [128][64] negated

    int tid = threadIdx.x;
    int qt = blockIdx.x & (NQT - 1);
    int kc = blockIdx.x >> 7;
    int q0 = qt * QT;
    int b  = q0 >> 10;
    int t0 = q0 & (T_ - 1);
    int k0 = kc * KCH;

    for (int e = tid; e < (D_*QT)/4; e += 256) {
        int d = e >> 4, q4 = e & 15;
        *(float4*)&h_s[d*QT + q4*4] =
            *(const float4*)&H[b*(D_*T_) + d*T_ + t0 + q4*4];
    }
    for (int e = tid; e < (D_*KCH)/4; e += 256) {
        int d = e >> 4, c4 = e & 15;
        float4 mv = *(const float4*)&M[d*K_ + k0 + c4*4];
        *(float4*)&m_s[d*KCH + c4*4] = make_float4(-mv.x, -mv.y, -mv.z, -mv.w);
    }
    __syncthreads();

    int tk = tid & 15, tq = tid >> 4;   // 16 k-groups x 16 q-groups
    int qq = tq * 4, kk = tk * 4;       // both LDS.128 conflict-free

    unsigned long long a00=0ULL,a01=0ULL,a10=0ULL,a11=0ULL;
    unsigned long long a20=0ULL,a21=0ULL,a30=0ULL,a31=0ULL;
    #pragma unroll 4
    for (int d = 0; d < D_; d++) {
        float4 hv = *(const float4*)&h_s[d*QT + qq];
        ulonglong2 mm = *(const ulonglong2*)&m_s[d*KCH + kk];   // (-k0,-k1),(-k2,-k3)
        unsigned long long H0 = dupf(hv.x), H1 = dupf(hv.y);
        unsigned long long H2 = dupf(hv.z), H3 = dupf(hv.w);
        a00 = fadd2u(a00, fadd2u(H0, mm.x) & ABSMASK);
        a01 = fadd2u(a01, fadd2u(H0, mm.y) & ABSMASK);
        a10 = fadd2u(a10, fadd2u(H1, mm.x) & ABSMASK);
        a11 = fadd2u(a11, fadd2u(H1, mm.y) & ABSMASK);
        a20 = fadd2u(a20, fadd2u(H2, mm.x) & ABSMASK);
        a21 = fadd2u(a21, fadd2u(H2, mm.y) & ABSMASK);
        a30 = fadd2u(a30, fadd2u(H3, mm.x) & ABSMASK);
        a31 = fadd2u(a31, fadd2u(H3, mm.y) & ABSMASK);
    }

    // thread-local lexmin per q over its 4 k (ascending k, strict <)
    int kb = k0 + kk;
    float bd[4]; int bi[4];
    unsigned long long p0[4] = {a00, a10, a20, a30};
    unsigned long long p1[4] = {a01, a11, a21, a31};
    #pragma unroll
    for (int iq = 0; iq < 4; iq++) {
        float c0 = __uint_as_float((unsigned)(p0[iq] & 0xffffffffu));
        float c1 = __uint_as_float((unsigned)(p0[iq] >> 32));
        float c2 = __uint_as_float((unsigned)(p1[iq] & 0xffffffffu));
        float c3 = __uint_as_float((unsigned)(p1[iq] >> 32));
        float bdv = c0; int biv = kb;
        if (c1 < bdv) { bdv = c1; biv = kb + 1; }
        if (c2 < bdv) { bdv = c2; biv = kb + 2; }
        if (c3 < bdv) { bdv = c3; biv = kb + 3; }
        bd[iq] = bdv; bi[iq] = biv;
    }

    // lexicographic min across the 16 tk lanes (first-argmin semantics)
    #pragma unroll
    for (int off = 1; off < 16; off <<= 1) {
        #pragma unroll
        for (int iq = 0; iq < 4; iq++) {
            float od = __shfl_xor_sync(0xffffffffu, bd[iq], off);
            int   oi = __shfl_xor_sync(0xffffffffu, bi[iq], off);
            if (od < bd[iq] || (od == bd[iq] && oi < bi[iq])) { bd[iq] = od; bi[iq] = oi; }
        }
    }
    if (tk == 0) {
        #pragma unroll
        for (int iq = 0; iq < 4; iq++) {
            g_bd[kc*Q_ + q0 + qq + iq] = bd[iq];
            g_bi[kc*Q_ + q0 + qq + iq] = bi[iq];
        }
    }
}

// ---------------- combine K-chunks, compute sum (h - z)^2 ----------------
__global__ void nnred_kernel(const float* __restrict__ H, const float* __restrict__ M) {
    int tid = threadIdx.x;
    int q = blockIdx.x * 256 + tid;
    float bd = g_bd[q]; int bi = g_bi[q];
    #pragma unroll
    for (int c = 1; c < NKC; c++) {
        float dd = g_bd[c*Q_ + q]; int ii = g_bi[c*Q_ + q];
        if (dd < bd) { bd = dd; bi = ii; }   // chunks ascend in k
    }
    int b = q >> 10, t = q & (T_ - 1);
    const float* h = H + b*(D_*T_) + t;
    float s = 0.f;
    #pragma unroll 8
    for (int d = 0; d < D_; d++) {
        float diff = h[d*T_] - M[d*K_ + bi];
        s += diff * diff;
    }
    #pragma unroll
    for (int off = 16; off > 0; off >>= 1) s += __shfl_down_sync(0xffffffffu, s, off);
    __shared__ float red[8];
    int warp = tid >> 5, lane = tid & 31;
    if (lane == 0) red[warp] = s;
    __syncthreads();
    if (tid == 0) {
        float tot = 0.f;
        #pragma unroll
        for (int i = 0; i < 8; i++) tot += red[i];
        atomicAdd(&g_acc[1], tot);
    }
}

// ---------------- dec_e: E = Hdec W^T - X -> g_E (STG), sumE^2 -------------
__global__ void dece_kernel(const float* __restrict__ Hdec, const float* __restrict__ W,
                            const float* __restrict__ X) {
    extern __shared__ char smem[];
    float* hd_s = (float*)smem;                // [16][256]  16KB
    float* w_s  = (float*)(smem + 16384);      // [256][33]  33KB padded
    __shared__ float red[8];

    int tid = threadIdx.x;
    int r0 = blockIdx.x * 16;
    int warp = tid >> 5, lane = tid & 31;

    for (int e = tid; e < C_*F_; e += 256) {
        int c = e >> 8, f = e & 255;
        w_s[f*33 + c] = W[e];
    }
    {
        const float4* src = (const float4*)(Hdec + (size_t)r0 * F_);
        float4* dst = (float4*)hd_s;
        #pragma unroll
        for (int i = 0; i < 4; i++) dst[tid + i*256] = src[tid + i*256];
    }
    __syncthreads();

    float acc0 = 0.f, acc1 = 0.f;
    for (int f = 0; f < F_; f += 4) {
        float w0 = w_s[(f+0)*33 + lane];
        float w1 = w_s[(f+1)*33 + lane];
        float w2 = w_s[(f+2)*33 + lane];
        float w3 = w_s[(f+3)*33 + lane];
        float4 a4 = *(const float4*)&hd_s[(warp*2    )*F_ + f];
        float4 b4 = *(const float4*)&hd_s[(warp*2 + 1)*F_ + f];
        acc0 = fmaf(a4.x, w0, fmaf(a4.y, w1, fmaf(a4.z, w2, fmaf(a4.w, w3, acc0))));
        acc1 = fmaf(b4.x, w0, fmaf(b4.y, w1, fmaf(b4.z, w2, fmaf(b4.w, w3, acc1))));
    }
    float e0 = acc0 - X[(size_t)(r0 + warp*2    )*C_ + lane];
    float e1 = acc1 - X[(size_t)(r0 + warp*2 + 1)*C_ + lane];
    g_E[(r0 + warp*2    )*C_ + lane] = e0;
    g_E[(r0 + warp*2 + 1)*C_ + lane] = e1;
    float s2 = e0*e0 + e1*e1;
    #pragma unroll
    for (int off = 16; off > 0; off >>= 1) s2 += __shfl_down_sync(0xffffffffu, s2, off);
    if (lane == 0) red[warp] = s2;
    __syncthreads();
    if (tid == 0) {
        float tot = 0.f;
        #pragma unroll
        for (int i = 0; i < 8; i++) tot += red[i];
        atomicAdd(&g_acc[0], tot);
    }
}

// ---------------- dec_g: G = E^T @ Hdec (tiled GEMM) + S partials ----------
__global__ void decg_kernel(const float* __restrict__ Hdec) {
    __shared__ float e_s[64*32];    //  8KB
    __shared__ float hd_s[64*64];   // 16KB
    int tid = threadIdx.x;
    int rc = blockIdx.x & 63, ft = blockIdx.x >> 6;
    int r0 = rc * 128, f0 = ft * 64;
    int tc = tid & 15, tf = tid >> 4;

    float ga[8] = {0,0,0,0,0,0,0,0};
    float scol = 0.f;

    for (int sub = 0; sub < 2; sub++) {
        int rr0 = r0 + sub*64;
        __syncthreads();
        {
            const float4* esrc = (const float4*)(g_E + (size_t)rr0 * C_);
            float4* edst = (float4*)e_s;
            edst[tid]       = esrc[tid];
            edst[tid + 256] = esrc[tid + 256];
            const float4* hsrc = (const float4*)(Hdec + (size_t)rr0 * F_ + f0);
            float4* hdst = (float4*)hd_s;
            #pragma unroll
            for (int i = 0; i < 4; i++) {
                int idx = tid + i*256;
                int row = idx >> 4, c4 = idx & 15;
                hdst[row*16 + c4] = hsrc[row*64 + c4];
            }
        }
        __syncthreads();
        #pragma unroll 4
        for (int r = 0; r < 64; r++) {
            float2 ec = *(const float2*)&e_s[r*32 + tc*2];
            float4 hv = *(const float4*)&hd_s[r*64 + tf*4];
            ga[0] += ec.x*hv.x; ga[1] += ec.x*hv.y; ga[2] += ec.x*hv.z; ga[3] += ec.x*hv.w;
            ga[4] += ec.y*hv.x; ga[5] += ec.y*hv.y; ga[6] += ec.y*hv.z; ga[7] += ec.y*hv.w;
        }
        if (tid < 64) {
            #pragma unroll 8
            for (int r = 0; r < 64; r++) scol += hd_s[r*64 + tid];
        }
    }

    if (tid < 64) atomicAdd(&g_S[f0 + tid], scol);
    float* gdst = &g_Gr[(rc & (NREP-1))*C_*F_];
    int c0 = tc*2, fbase = f0 + tf*4;
    #pragma unroll
    for (int j = 0; j < 4; j++) {
        atomicAdd(&gdst[(c0    )*F_ + fbase + j], ga[j]);
        atomicAdd(&gdst[(c0 + 1)*F_ + fbase + j], ga[4 + j]);
    }
}

// ---------------- final scalar assembly (1024 threads, shuffle reduce) -----
__global__ void final_kernel(const float* __restrict__ W, const float* __restrict__ w_d,
                             float* __restrict__ out) {
    __shared__ float4 red4[32];
    int tid = threadIdx.x, lane = tid & 31, warp = tid >> 5;

    float sG = 0.f, sWS = 0.f;
    #pragma unroll
    for (int i = tid; i < C_*F_; i += 1024) {
        float g = g_Gr[i] + g_Gr[C_*F_ + i] + g_Gr[2*C_*F_ + i] + g_Gr[3*C_*F_ + i];
        sG  += g * g;
        sWS += W[i] * g_S[i & 255] * w_d[i >> 8];
    }
    float sS  = (tid < F_) ? g_S[tid]*g_S[tid] : 0.f;
    float wd2 = (tid < C_) ? w_d[tid]*w_d[tid] : 0.f;

    #pragma unroll
    for (int off = 16; off > 0; off >>= 1) {
        sG  += __shfl_down_sync(0xffffffffu, sG,  off);
        sWS += __shfl_down_sync(0xffffffffu, sWS, off);
        sS  += __shfl_down_sync(0xffffffffu, sS,  off);
        wd2 += __shfl_down_sync(0xffffffffu, wd2, off);
    }
    if (lane == 0) red4[warp] = make_float4(sG, sWS, sS, wd2);
    __syncthreads();
    if (warp == 0) {
        float4 v = red4[lane];
        #pragma unroll
        for (int off = 16; off > 0; off >>= 1) {
            v.x += __shfl_down_sync(0xffffffffu, v.x, off);
            v.y += __shfl_down_sync(0xffffffffu, v.y, off);
            v.z += __shfl_down_sync(0xffffffffu, v.z, off);
            v.w += __shfl_down_sync(0xffffffffu, v.w, off);
        }
        if (lane == 0) {
            float loss_rec = g_acc[0] / 262144.f;                 // mean over B*T*C
            float loss_m   = 2.f * g_acc[1] / 1048576.f;          // 2*sum/(B*D*T)
            float normGrec = (2.f / 262144.f) * sqrtf(v.x);       // ||g_rec||_F
            float normGd   = sqrtf(v.w) * sqrtf(v.z) / 8192.f;    // ||g_d||_F (rank-1)
            float lmbda    = normGrec / (normGd + 1e-6f);
            float loss_d   = -v.y / 8192.f;
            out[0] = loss_rec + loss_m + lmbda * loss_d;
        }
    }
}

extern "C" void kernel_launch(void* const* d_in, const int* in_sizes, int n_in,
                              void* d_out, int out_size) {
    const float* X    = (const float*)d_in[0];
    const float* H    = (const float*)d_in[1];
    const float* M    = (const float*)d_in[2];
    const float* Hdec = (const float*)d_in[3];
    const float* W    = (const float*)d_in[4];
    const float* w_d  = (const float*)d_in[5];
    float* out = (float*)d_out;
    (void)in_sizes; (void)n_in; (void)out_size;

    static int init_done = 0;
    static cudaStream_t s2;
    static cudaEvent_t ev_fork, ev_join;
    if (!init_done) {
        cudaFuncSetAttribute(nn6_kernel,  cudaFuncAttributeMaxDynamicSharedMemorySize, 65536);
        cudaFuncSetAttribute(dece_kernel, cudaFuncAttributeMaxDynamicSharedMemorySize, 50176);
        cudaStreamCreateWithFlags(&s2, cudaStreamNonBlocking);
        cudaEventCreateWithFlags(&ev_fork, cudaEventDisableTiming);
        cudaEventCreateWithFlags(&ev_join, cudaEventDisableTiming);
        init_done = 1;
    }

    // fork: decoder chain on s2 overlaps the NN chain on the capture stream
    cudaEventRecord(ev_fork, 0);
    cudaStreamWaitEvent(s2, ev_fork, 0);

    zero_kernel <<<(NREP*C_*F_ + 255)/256, 256, 0, s2>>>();
    dece_kernel <<<Q_/16, 256, 50176, s2>>>(Hdec, W, X);   // 512 CTAs
    decg_kernel <<<256, 256, 0, s2>>>(Hdec);               // 256 CTAs

    nn6_kernel  <<<NQT*NKC, 256, 65536>>>(H, M);           // 1024 CTAs: hot kernel
    nnred_kernel<<<Q_/256, 256>>>(H, M);

    cudaEventRecord(ev_join, s2);
    cudaStreamWaitEvent(0, ev_join, 0);
    final_kernel<<<1, 1024>>>(W, w_d, out);
}